// round 5
// baseline (speedup 1.0000x reference)
#include <cuda_runtime.h>
#include <math.h>

#define NEGF    (-1e30f)
#define MAXB    16
#define NCH     32
#define LOG2E_F 1.4426950408889634f
#define LN2_F   0.6931471805599453f
#define PEI_NONE (-1000000000)

// Scratch (static device arrays; no allocations allowed)
__device__ float    g_num[MAXB];                 // numerator logZ per batch (natural log)
__device__ float    g_LP[MAXB * NCH * 8 * 8];    // [b][c][j][i] log chunk matrices
__device__ unsigned g_done = 0;

// ---------------- helpers ----------------
__device__ __forceinline__ float ex2f_(float x) {
    float r; asm("ex2.approx.ftz.f32 %0, %1;" : "=f"(r) : "f"(x)); return r;
}
__device__ __forceinline__ float lg2f_(float x) {
    float r; asm("lg2.approx.ftz.f32 %0, %1;" : "=f"(r) : "f"(x)); return r;
}
// logaddexp in log2 domain: log2(2^a + 2^b)
__device__ __forceinline__ float lae2(float a, float b) {
    float m = fmaxf(a, b);
    float d = fminf(a, b) - m;            // <= 0
    return m + lg2f_(1.0f + ex2f_(d));
}
// volatile 128-bit shared ld/st (single LDS.128/STS.128; .x doubles as ready flag)
__device__ __forceinline__ float4 lds128v(const float4* p) {
    float4 v; unsigned a = (unsigned)__cvta_generic_to_shared(p);
    asm volatile("ld.volatile.shared.v4.f32 {%0,%1,%2,%3},[%4];"
                 : "=f"(v.x), "=f"(v.y), "=f"(v.z), "=f"(v.w) : "r"(a));
    return v;
}
__device__ __forceinline__ void sts128v(float4* p, float4 v) {
    unsigned a = (unsigned)__cvta_generic_to_shared(p);
    asm volatile("st.volatile.shared.v4.f32 [%0],{%1,%2,%3,%4};"
                 :: "r"(a), "f"(v.x), "f"(v.y), "f"(v.z), "f"(v.w));
}
__device__ __forceinline__ int isnanf_(float x) { return x != x; }

// One numerator step, LINEAR space with per-lane block exponent e (value = v * 2^e).
// Thread owns target lanes u0=2k, u1=2k+1. CUR_ feeds lane 0's boundary.
#define NUM_STEP(T_, J_, CUR_, RESC_) do {                                     \
    float pe_ = __shfl_up_sync(0xffffffffu, ve1, 1);                           \
    float px_ = __shfl_up_sync(0xffffffffu, vx1, 1);                           \
    int  pei_ = __shfl_up_sync(0xffffffffu, e, 1);                             \
    if (lane == 0) { pe_ = (CUR_).x; px_ = (CUR_).y;                           \
                     pei_ = __float_as_int((CUR_).z); }                        \
    int d_  = pei_ - e;                                                        \
    int dp_ = max(d_, 0);                                                      \
    int dn_ = min(d_, 0);                                                      \
    float fo_ = __int_as_float((max(-dp_, -127) + 127) << 23);  /* own scale */\
    float fi_ = __int_as_float((max(dn_, -127) + 127) << 23);   /* in  scale */\
    e += dp_;                                                                  \
    float g0_ = eme0[J_] * fi_;                                                \
    float g1_ = emx0[J_] * fo_;                                                \
    float g2_ = eme1[J_] * fo_;                                                \
    float g3_ = emx1[J_] * fo_;                                                \
    float nve0_ = g0_ * fmaf(pe_, t_ee0, px_ * t_xe0);                         \
    float nvx0_ = g1_ * fmaf(ve0, t_ex0, vx0 * t_xx0);                         \
    float nve1_ = g2_ * fmaf(ve0, t_ee1, vx0 * t_xe1);                         \
    float nvx1_ = g3_ * fmaf(ve1, t_ex1, vx1 * t_xx1);                         \
    int tp_ = min((T_) + 4, len - 1);                                          \
    eme0[J_] = ex2f_(__ldg(emb + tp_ * 8 + es0) * LOG2E_F);                    \
    emx0[J_] = ex2f_(__ldg(emb + tp_ * 8 + xs0) * LOG2E_F);                    \
    eme1[J_] = ex2f_(__ldg(emb + tp_ * 8 + es1) * LOG2E_F);                    \
    emx1[J_] = ex2f_(__ldg(emb + tp_ * 8 + xs1) * LOG2E_F);                    \
    ve0 = nve0_; vx0 = nvx0_; ve1 = nve1_; vx1 = nvx1_;                        \
    if (lane == 31 && warp < 3 && (T_) <= lenm2)                               \
        sts128v(&rprod[(T_)], make_float4(ve1, vx1, __int_as_float(e), 0.f));  \
    if (RESC_) {                                                               \
        float m_ = fmaxf(fmaxf(ve0, vx0), fmaxf(ve1, vx1));                    \
        int mb_ = __float_as_int(m_);                                          \
        int ei_ = (mb_ == 0) ? 0 : ((mb_ >> 23) - 127);                        \
        float fr_ = __int_as_float((127 - ei_) << 23);                         \
        ve0 *= fr_; vx0 *= fr_; ve1 *= fr_; vx1 *= fr_;                        \
        e += ei_;                                                              \
    }                                                                          \
} while (0)

extern "C" __global__ void __launch_bounds__(256, 1)
ctccrf_fused(const float* __restrict__ em,      // (B,T,8)
             const float* __restrict__ trans,   // (8,8)
             const float* __restrict__ bos,     // (8)
             const float* __restrict__ eos,     // (8)
             const int*   __restrict__ lengths, // (B)
             const int*   __restrict__ targets, // (B,L)
             const int*   __restrict__ tlens,   // (B)
             float* __restrict__ out,
             int B, int T, int L)
{
    extern __shared__ float4 dring[];           // [3][T-1] boundary slots
    __shared__ float s_scratch[MAXB];
    __shared__ int   s_flag;
    const int tid = threadIdx.x;
    const int RNn = T - 1;

    if ((int)blockIdx.x < B) {
        // ------- Numerator: 128 workers, 2 lanes/thread, linear space, skewed warps -------
        const float NANSENT = __int_as_float(0x7fc00000);
        for (int i = tid; i < 3 * RNn; i += 256)
            dring[i] = make_float4(NANSENT, 0.f, 0.f, 0.f);
        __syncthreads();

        if (tid < (L >> 1)) {
            const int b    = blockIdx.x;
            const int k    = tid;
            const int lane = k & 31;
            const int warp = k >> 5;
            const int u0 = 2 * k, u1 = 2 * k + 1;

            const int len = lengths[b];
            const int lenm2 = len - 2;
            const int tg0 = __ldg(targets + b * L + u0);
            const int tg1 = __ldg(targets + b * L + u1);
            const int es0 = tg0, xs0 = tg0 + 4;
            const int es1 = tg1, xs1 = tg1 + 4;
            const int tgp0 = (u0 == 0) ? tg0 : __ldg(targets + b * L + u0 - 1);

            // transitions in LINEAR space
            const float t_ee0 = __expf(__ldg(trans + tgp0 * 8 + es0));
            const float t_xe0 = __expf(__ldg(trans + (tgp0 + 4) * 8 + es0));
            const float t_ex0 = __expf(__ldg(trans + es0 * 8 + xs0));
            const float t_xx0 = __expf(__ldg(trans + xs0 * 8 + xs0));
            const float t_ee1 = __expf(__ldg(trans + tg0 * 8 + es1));  // prev of u1 is u0
            const float t_xe1 = __expf(__ldg(trans + (tg0 + 4) * 8 + es1));
            const float t_ex1 = __expf(__ldg(trans + es1 * 8 + xs1));
            const float t_xx1 = __expf(__ldg(trans + xs1 * 8 + xs1));

            const float* emb = em + (size_t)b * T * 8;
            float ve0 = (u0 == 0) ? __expf(__ldg(bos + es0) + __ldg(emb + es0)) : 0.f;
            float vx0 = 0.f, ve1 = 0.f, vx1 = 0.f;
            int e = 0;

            float4*       rprod = dring + (size_t)((warp < 3) ? warp : 0) * RNn;
            const float4* rcons = dring + (size_t)((warp > 0) ? (warp - 1) : 0) * RNn;

            // publish initial boundary (time 0)
            if (lane == 31 && warp < 3)
                sts128v(&rprod[0], make_float4(ve1, vx1, __int_as_float(e), 0.f));

            // emission prefetch for steps 1..4 (clamped), LINEAR
            float eme0[4], emx0[4], eme1[4], emx1[4];
            #pragma unroll
            for (int j = 0; j < 4; ++j) {
                int tc = min(1 + j, len - 1);
                eme0[j] = ex2f_(__ldg(emb + tc * 8 + es0) * LOG2E_F);
                emx0[j] = ex2f_(__ldg(emb + tc * 8 + xs0) * LOG2E_F);
                eme1[j] = ex2f_(__ldg(emb + tc * 8 + es1) * LOG2E_F);
                emx1[j] = ex2f_(__ldg(emb + tc * 8 + xs1) * LOG2E_F);
            }

            const float4 W0C = make_float4(0.f, 0.f, __int_as_float(PEI_NONE), 0.f);
            float4 cur0 = W0C, cur1 = W0C, cur2 = W0C, cur3 = W0C;
            float4 nxt0 = W0C, nxt1 = W0C, nxt2 = W0C, nxt3 = W0C;
            if (lane == 0 && warp > 0) {
                cur0 = lds128v(&rcons[0]);
                cur1 = lds128v(&rcons[min(1, lenm2)]);
                cur2 = lds128v(&rcons[min(2, lenm2)]);
                cur3 = lds128v(&rcons[min(3, lenm2)]);
            }

            int t = 1;
            for (; t + 3 < len; t += 4) {
                if (lane == 0 && warp > 0) {
                    while (isnanf_(cur0.x) | isnanf_(cur1.x) | isnanf_(cur2.x) | isnanf_(cur3.x)) {
                        cur0 = lds128v(&rcons[t - 1]);
                        cur1 = lds128v(&rcons[t]);
                        cur2 = lds128v(&rcons[t + 1]);
                        cur3 = lds128v(&rcons[t + 2]);
                    }
                    nxt0 = lds128v(&rcons[min(t + 3, lenm2)]);
                    nxt1 = lds128v(&rcons[min(t + 4, lenm2)]);
                    nxt2 = lds128v(&rcons[min(t + 5, lenm2)]);
                    nxt3 = lds128v(&rcons[min(t + 6, lenm2)]);
                }
                NUM_STEP(t,     0, cur0, 0);
                NUM_STEP(t + 1, 1, cur1, 1);
                NUM_STEP(t + 2, 2, cur2, 0);
                NUM_STEP(t + 3, 3, cur3, 1);
                cur0 = nxt0; cur1 = nxt1; cur2 = nxt2; cur3 = nxt3;
            }
            // tail (<=3 steps; len uniform across block)
            if (t < len) {
                float4 bb = W0C;
                if (lane == 0 && warp > 0) { do { bb = lds128v(&rcons[t - 1]); } while (isnanf_(bb.x)); }
                NUM_STEP(t, 0, bb, 1); t++;
            }
            if (t < len) {
                float4 bb = W0C;
                if (lane == 0 && warp > 0) { do { bb = lds128v(&rcons[t - 1]); } while (isnanf_(bb.x)); }
                NUM_STEP(t, 1, bb, 1); t++;
            }
            if (t < len) {
                float4 bb = W0C;
                if (lane == 0 && warp > 0) { do { bb = lds128v(&rcons[t - 1]); } while (isnanf_(bb.x)); }
                NUM_STEP(t, 2, bb, 1); t++;
            }

            const int tl = __ldg(tlens + b);
            if (u0 == tl - 1) {
                float fe2 = lg2f_(ve0) + (float)e + __ldg(eos + es0) * LOG2E_F;
                float fx2 = lg2f_(vx0) + (float)e + __ldg(eos + xs0) * LOG2E_F;
                g_num[b] = lae2(fe2, fx2) * LN2_F;
            }
            if (u1 == tl - 1) {
                float fe2 = lg2f_(ve1) + (float)e + __ldg(eos + es1) * LOG2E_F;
                float fx2 = lg2f_(vx1) + (float)e + __ldg(eos + xs1) * LOG2E_F;
                g_num[b] = lae2(fe2, fx2) * LN2_F;
            }
        }
    } else {
        // ------------- Denominator Phase A: chunked 8x8 linear-space scan -------------
        const int db = blockIdx.x - B;          // batch (grid is exactly 2B)
        const int c = tid >> 3;                 // chunk 0..31
        const int i = tid & 7;                  // row of chunk matrix
        const int len = lengths[db];
        const int C = (T - 1 + NCH - 1) / NCH;

        float E[64];
        #pragma unroll
        for (int k = 0; k < 64; ++k) E[k] = __expf(__ldg(trans + k));

        float r[8];
        #pragma unroll
        for (int j = 0; j < 8; ++j) r[j] = (j == i) ? 1.0f : 0.0f;
        float off = 0.0f;

        const int t0 = 1 + c * C;
        const int t1 = min(t0 + C, len);
        const float* emb = em + (size_t)db * T * 8;

        for (int t = t0; t < t1; ++t) {
            float4 lo = __ldg((const float4*)(emb + t * 8));
            float4 hi = __ldg((const float4*)(emb + t * 8 + 4));
            float Em[8];
            Em[0] = __expf(lo.x); Em[1] = __expf(lo.y);
            Em[2] = __expf(lo.z); Em[3] = __expf(lo.w);
            Em[4] = __expf(hi.x); Em[5] = __expf(hi.y);
            Em[6] = __expf(hi.z); Em[7] = __expf(hi.w);

            float s[8];
            #pragma unroll
            for (int j = 0; j < 8; ++j) {
                float acc = r[0] * E[0 * 8 + j];
                #pragma unroll
                for (int kk = 1; kk < 8; ++kk) acc = fmaf(r[kk], E[kk * 8 + j], acc);
                s[j] = acc * Em[j];
            }
            #pragma unroll
            for (int j = 0; j < 8; ++j) r[j] = s[j];

            if (((t - t0) & 3) == 3) {
                float m = r[0];
                #pragma unroll
                for (int j = 1; j < 8; ++j) m = fmaxf(m, r[j]);
                float inv = __fdividef(1.0f, m);
                off += __logf(m);
                #pragma unroll
                for (int j = 0; j < 8; ++j) r[j] *= inv;
            }
        }

        #pragma unroll
        for (int j = 0; j < 8; ++j) {
            float lv = (r[j] > 0.0f) ? (__logf(r[j]) + off) : NEGF;
            g_LP[(((db * NCH) + c) * 8 + j) * 8 + i] = lv;
        }
    }

    // ---------------- Fused finish: last block folds chunks + reduces ----------------
    __threadfence();
    __syncthreads();
    if (tid == 0) {
        unsigned old = atomicAdd(&g_done, 1u);
        s_flag = (old == (unsigned)(2 * B - 1));
    }
    __syncthreads();
    if (s_flag) {
        __threadfence();
        const int  bq = min(tid >> 3, B - 1);   // clamp so all 256 threads run shfls
        const int  j  = tid & 7;
        const bool active = (tid >> 3) < B;

        float alpha = __ldg(bos + j) + __ldg(em + (size_t)bq * T * 8 + j);  // natural log
        const float* base = g_LP + (size_t)bq * NCH * 64 + j * 8;
        float4 plo[4], phi[4];
        #pragma unroll
        for (int kk = 0; kk < 4; ++kk) {
            plo[kk] = __ldg((const float4*)(base + kk * 64));
            phi[kk] = __ldg((const float4*)(base + kk * 64 + 4));
        }
        #pragma unroll 4
        for (int c = 0; c < NCH; ++c) {
            float4 lo = plo[c & 3], hi = phi[c & 3];
            int cn = c + 4;
            if (cn < NCH) {
                plo[c & 3] = __ldg((const float4*)(base + cn * 64));
                phi[c & 3] = __ldg((const float4*)(base + cn * 64 + 4));
            }
            float M[8] = {lo.x, lo.y, lo.z, lo.w, hi.x, hi.y, hi.z, hi.w};
            float v[8], m = -3.0e38f;
            #pragma unroll
            for (int i2 = 0; i2 < 8; ++i2) {
                float ai = __shfl_sync(0xffffffffu, alpha, i2, 8);
                v[i2] = ai + M[i2];
                m = fmaxf(m, v[i2]);
            }
            float s = 0.0f;
            #pragma unroll
            for (int i2 = 0; i2 < 8; ++i2) s += ex2f_((v[i2] - m) * LOG2E_F);
            alpha = m + lg2f_(s) * LN2_F;
        }
        float f = alpha + __ldg(eos + j);
        float m = f;
        #pragma unroll
        for (int d = 4; d >= 1; d >>= 1) m = fmaxf(m, __shfl_xor_sync(0xffffffffu, m, d, 8));
        float s = ex2f_((f - m) * LOG2E_F);
        #pragma unroll
        for (int d = 4; d >= 1; d >>= 1) s += __shfl_xor_sync(0xffffffffu, s, d, 8);
        float den = m + lg2f_(s) * LN2_F;

        if (active && j == 0) s_scratch[tid >> 3] = den - g_num[bq];
        __syncthreads();
        if (tid == 0) {
            float acc = 0.0f;
            for (int bb = 0; bb < B; ++bb) acc += s_scratch[bb];
            out[0] = acc / (float)B;
            g_done = 0;                         // reset for next graph replay
        }
    }
}

extern "C" void kernel_launch(void* const* d_in, const int* in_sizes, int n_in,
                              void* d_out, int out_size)
{
    const float* em     = (const float*)d_in[0];  // (B,T,8)
    const float* trans  = (const float*)d_in[1];  // (8,8)
    const float* bos    = (const float*)d_in[2];  // (8)
    const float* eos    = (const float*)d_in[3];  // (8)
    const int*   lens   = (const int*)  d_in[4];  // (B)
    const int*   tgts   = (const int*)  d_in[5];  // (B,L)
    const int*   tlens  = (const int*)  d_in[6];  // (B)
    float* out = (float*)d_out;

    const int B = in_sizes[4];                 // 16
    const int T = in_sizes[0] / (B * 8);       // 2048
    const int L = in_sizes[5] / B;             // 256

    const size_t smem = (size_t)3 * (T - 1) * sizeof(float4);  // boundary rings
    cudaFuncSetAttribute(ctccrf_fused, cudaFuncAttributeMaxDynamicSharedMemorySize, (int)smem);

    // Blocks [0,B): numerator (L/2 workers, linear-space, sentinel-ring skewed warps).
    // Blocks [B,2B): denominator phase A. Last-done block runs the finish fold.
    ctccrf_fused<<<2 * B, 256, smem>>>(em, trans, bos, eos, lens, tgts, tlens, out, B, T, L);
}

// round 6
// speedup vs baseline: 1.1338x; 1.1338x over previous
#include <cuda_runtime.h>
#include <math.h>

#define NEGF    (-1e30f)
#define MAXB    16
#define NCH     32
#define LOG2E_F 1.4426950408889634f
#define LN2_F   0.6931471805599453f
#define PEI_NONE (-1000000000)

// Scratch (static device arrays; no allocations allowed)
__device__ float    g_num[MAXB];                 // numerator logZ per batch (natural log)
__device__ float    g_LP[MAXB * NCH * 8 * 8];    // [b][c][j][i] log chunk matrices
__device__ unsigned g_done = 0;

// ---------------- helpers ----------------
__device__ __forceinline__ float ex2f_(float x) {
    float r; asm("ex2.approx.ftz.f32 %0, %1;" : "=f"(r) : "f"(x)); return r;
}
__device__ __forceinline__ float lg2f_(float x) {
    float r; asm("lg2.approx.ftz.f32 %0, %1;" : "=f"(r) : "f"(x)); return r;
}
// logaddexp in log2 domain: log2(2^a + 2^b)
__device__ __forceinline__ float lae2(float a, float b) {
    float m = fmaxf(a, b);
    float d = fminf(a, b) - m;            // <= 0
    return m + lg2f_(1.0f + ex2f_(d));
}
// volatile 128-bit shared ld/st (single LDS.128/STS.128; .x doubles as ready flag)
__device__ __forceinline__ float4 lds128v(const float4* p) {
    float4 v; unsigned a = (unsigned)__cvta_generic_to_shared(p);
    asm volatile("ld.volatile.shared.v4.f32 {%0,%1,%2,%3},[%4];"
                 : "=f"(v.x), "=f"(v.y), "=f"(v.z), "=f"(v.w) : "r"(a));
    return v;
}
__device__ __forceinline__ void sts128v(float4* p, float4 v) {
    unsigned a = (unsigned)__cvta_generic_to_shared(p);
    asm volatile("st.volatile.shared.v4.f32 [%0],{%1,%2,%3,%4};"
                 :: "r"(a), "f"(v.x), "f"(v.y), "f"(v.z), "f"(v.w));
}
__device__ __forceinline__ int isnanf_(float x) { return x != x; }

// One numerator step, LINEAR space with per-lane block exponent e (value = v * 2^e).
// Emission pipeline (per slot J_):  use emX[J_] (step T_)  ->  convert rawX[J_]
// (logit for T_+4, loaded at T_-4)  ->  load rawX[J_] = logit for T_+8 (no
// dependent op; consumed 4 steps later, so the LDG scoreboard never stalls us).
#define NUM_STEP(T_, J_, CUR_, RESC_) do {                                     \
    float pe_ = __shfl_up_sync(0xffffffffu, ve1, 1);                           \
    float px_ = __shfl_up_sync(0xffffffffu, vx1, 1);                           \
    int  pei_ = __shfl_up_sync(0xffffffffu, e, 1);                             \
    if (lane == 0) { pe_ = (CUR_).x; px_ = (CUR_).y;                           \
                     pei_ = __float_as_int((CUR_).z); }                        \
    int d_  = pei_ - e;                                                        \
    int dp_ = max(d_, 0);                                                      \
    int dn_ = min(d_, 0);                                                      \
    float fo_ = __int_as_float((max(-dp_, -127) + 127) << 23);  /* own scale */\
    float fi_ = __int_as_float((max(dn_, -127) + 127) << 23);   /* in  scale */\
    e += dp_;                                                                  \
    float g0_ = eme0[J_] * fi_;                                                \
    float g1_ = emx0[J_] * fo_;                                                \
    float g2_ = eme1[J_] * fo_;                                                \
    float g3_ = emx1[J_] * fo_;                                                \
    float nve0_ = g0_ * fmaf(pe_, t_ee0, px_ * t_xe0);                         \
    float nvx0_ = g1_ * fmaf(ve0, t_ex0, vx0 * t_xx0);                         \
    float nve1_ = g2_ * fmaf(ve0, t_ee1, vx0 * t_xe1);                         \
    float nvx1_ = g3_ * fmaf(ve1, t_ex1, vx1 * t_xx1);                         \
    /* convert raw logits (loaded 4 steps ago) for step T_+4 */                \
    eme0[J_] = ex2f_(rawe0[J_] * LOG2E_F);                                     \
    emx0[J_] = ex2f_(rawx0[J_] * LOG2E_F);                                     \
    eme1[J_] = ex2f_(rawe1[J_] * LOG2E_F);                                     \
    emx1[J_] = ex2f_(rawx1[J_] * LOG2E_F);                                     \
    /* issue loads for step T_+8 (no dependent op this step) */                \
    int tp_ = min((T_) + 8, len - 1);                                          \
    rawe0[J_] = __ldg(emb + tp_ * 8 + es0);                                    \
    rawx0[J_] = __ldg(emb + tp_ * 8 + xs0);                                    \
    rawe1[J_] = __ldg(emb + tp_ * 8 + es1);                                    \
    rawx1[J_] = __ldg(emb + tp_ * 8 + xs1);                                    \
    ve0 = nve0_; vx0 = nvx0_; ve1 = nve1_; vx1 = nvx1_;                        \
    if (lane == 31 && warp < 3 && (T_) <= lenm2)                               \
        sts128v(&rprod[(T_)], make_float4(ve1, vx1, __int_as_float(e), 0.f));  \
    if (RESC_) {                                                               \
        float m_ = fmaxf(fmaxf(ve0, vx0), fmaxf(ve1, vx1));                    \
        int mb_ = __float_as_int(m_);                                          \
        int ei_ = (mb_ == 0) ? 0 : ((mb_ >> 23) - 127);                        \
        float fr_ = __int_as_float((127 - ei_) << 23);                         \
        ve0 *= fr_; vx0 *= fr_; ve1 *= fr_; vx1 *= fr_;                        \
        e += ei_;                                                              \
    }                                                                          \
} while (0)

extern "C" __global__ void __launch_bounds__(256, 1)
ctccrf_fused(const float* __restrict__ em,      // (B,T,8)
             const float* __restrict__ trans,   // (8,8)
             const float* __restrict__ bos,     // (8)
             const float* __restrict__ eos,     // (8)
             const int*   __restrict__ lengths, // (B)
             const int*   __restrict__ targets, // (B,L)
             const int*   __restrict__ tlens,   // (B)
             float* __restrict__ out,
             int B, int T, int L)
{
    extern __shared__ float4 dring[];           // [3][T-1] boundary slots
    __shared__ float s_scratch[MAXB];
    __shared__ int   s_flag;
    const int tid = threadIdx.x;
    const int RNn = T - 1;

    if ((int)blockIdx.x < B) {
        // ------- Numerator: 128 workers, 2 lanes/thread, linear space, skewed warps -------
        const float NANSENT = __int_as_float(0x7fc00000);
        for (int i = tid; i < 3 * RNn; i += 256)
            dring[i] = make_float4(NANSENT, 0.f, 0.f, 0.f);
        __syncthreads();

        if (tid < (L >> 1)) {
            const int b    = blockIdx.x;
            const int k    = tid;
            const int lane = k & 31;
            const int warp = k >> 5;
            const int u0 = 2 * k, u1 = 2 * k + 1;

            const int len = lengths[b];
            const int lenm2 = len - 2;
            const int tg0 = __ldg(targets + b * L + u0);
            const int tg1 = __ldg(targets + b * L + u1);
            const int es0 = tg0, xs0 = tg0 + 4;
            const int es1 = tg1, xs1 = tg1 + 4;
            const int tgp0 = (u0 == 0) ? tg0 : __ldg(targets + b * L + u0 - 1);

            // transitions in LINEAR space
            const float t_ee0 = __expf(__ldg(trans + tgp0 * 8 + es0));
            const float t_xe0 = __expf(__ldg(trans + (tgp0 + 4) * 8 + es0));
            const float t_ex0 = __expf(__ldg(trans + es0 * 8 + xs0));
            const float t_xx0 = __expf(__ldg(trans + xs0 * 8 + xs0));
            const float t_ee1 = __expf(__ldg(trans + tg0 * 8 + es1));  // prev of u1 is u0
            const float t_xe1 = __expf(__ldg(trans + (tg0 + 4) * 8 + es1));
            const float t_ex1 = __expf(__ldg(trans + es1 * 8 + xs1));
            const float t_xx1 = __expf(__ldg(trans + xs1 * 8 + xs1));

            const float* emb = em + (size_t)b * T * 8;
            float ve0 = (u0 == 0) ? __expf(__ldg(bos + es0) + __ldg(emb + es0)) : 0.f;
            float vx0 = 0.f, ve1 = 0.f, vx1 = 0.f;
            int e = 0;

            float4*       rprod = dring + (size_t)((warp < 3) ? warp : 0) * RNn;
            const float4* rcons = dring + (size_t)((warp > 0) ? (warp - 1) : 0) * RNn;

            // publish initial boundary (time 0)
            if (lane == 31 && warp < 3)
                sts128v(&rprod[0], make_float4(ve1, vx1, __int_as_float(e), 0.f));

            // emission pipeline priming:
            //   converted emX[j]  = emission for steps 1..4
            //   raw     rawX[j]   = logits  for steps 5..8
            float eme0[4], emx0[4], eme1[4], emx1[4];
            float rawe0[4], rawx0[4], rawe1[4], rawx1[4];
            #pragma unroll
            for (int j = 0; j < 4; ++j) {
                int tc = min(1 + j, len - 1);
                eme0[j] = ex2f_(__ldg(emb + tc * 8 + es0) * LOG2E_F);
                emx0[j] = ex2f_(__ldg(emb + tc * 8 + xs0) * LOG2E_F);
                eme1[j] = ex2f_(__ldg(emb + tc * 8 + es1) * LOG2E_F);
                emx1[j] = ex2f_(__ldg(emb + tc * 8 + xs1) * LOG2E_F);
                int tr = min(5 + j, len - 1);
                rawe0[j] = __ldg(emb + tr * 8 + es0);
                rawx0[j] = __ldg(emb + tr * 8 + xs0);
                rawe1[j] = __ldg(emb + tr * 8 + es1);
                rawx1[j] = __ldg(emb + tr * 8 + xs1);
            }

            const float4 W0C = make_float4(0.f, 0.f, __int_as_float(PEI_NONE), 0.f);
            float4 cur0 = W0C, cur1 = W0C, cur2 = W0C, cur3 = W0C;
            float4 nxt0 = W0C, nxt1 = W0C, nxt2 = W0C, nxt3 = W0C;
            if (lane == 0 && warp > 0) {
                cur0 = lds128v(&rcons[0]);
                cur1 = lds128v(&rcons[min(1, lenm2)]);
                cur2 = lds128v(&rcons[min(2, lenm2)]);
                cur3 = lds128v(&rcons[min(3, lenm2)]);
            }

            int t = 1;
            for (; t + 3 < len; t += 4) {
                if (lane == 0 && warp > 0) {
                    while (isnanf_(cur0.x) | isnanf_(cur1.x) | isnanf_(cur2.x) | isnanf_(cur3.x)) {
                        cur0 = lds128v(&rcons[t - 1]);
                        cur1 = lds128v(&rcons[t]);
                        cur2 = lds128v(&rcons[t + 1]);
                        cur3 = lds128v(&rcons[t + 2]);
                    }
                    nxt0 = lds128v(&rcons[min(t + 3, lenm2)]);
                    nxt1 = lds128v(&rcons[min(t + 4, lenm2)]);
                    nxt2 = lds128v(&rcons[min(t + 5, lenm2)]);
                    nxt3 = lds128v(&rcons[min(t + 6, lenm2)]);
                }
                NUM_STEP(t,     0, cur0, 0);
                NUM_STEP(t + 1, 1, cur1, 1);
                NUM_STEP(t + 2, 2, cur2, 0);
                NUM_STEP(t + 3, 3, cur3, 1);
                cur0 = nxt0; cur1 = nxt1; cur2 = nxt2; cur3 = nxt3;
            }
            // tail (<=3 steps; len uniform across block)
            if (t < len) {
                float4 bb = W0C;
                if (lane == 0 && warp > 0) { do { bb = lds128v(&rcons[t - 1]); } while (isnanf_(bb.x)); }
                NUM_STEP(t, 0, bb, 1); t++;
            }
            if (t < len) {
                float4 bb = W0C;
                if (lane == 0 && warp > 0) { do { bb = lds128v(&rcons[t - 1]); } while (isnanf_(bb.x)); }
                NUM_STEP(t, 1, bb, 1); t++;
            }
            if (t < len) {
                float4 bb = W0C;
                if (lane == 0 && warp > 0) { do { bb = lds128v(&rcons[t - 1]); } while (isnanf_(bb.x)); }
                NUM_STEP(t, 2, bb, 1); t++;
            }

            const int tl = __ldg(tlens + b);
            if (u0 == tl - 1) {
                float fe2 = lg2f_(ve0) + (float)e + __ldg(eos + es0) * LOG2E_F;
                float fx2 = lg2f_(vx0) + (float)e + __ldg(eos + xs0) * LOG2E_F;
                g_num[b] = lae2(fe2, fx2) * LN2_F;
            }
            if (u1 == tl - 1) {
                float fe2 = lg2f_(ve1) + (float)e + __ldg(eos + es1) * LOG2E_F;
                float fx2 = lg2f_(vx1) + (float)e + __ldg(eos + xs1) * LOG2E_F;
                g_num[b] = lae2(fe2, fx2) * LN2_F;
            }
        }
    } else {
        // ------------- Denominator Phase A: chunked 8x8 linear-space scan -------------
        const int db = blockIdx.x - B;          // batch (grid is exactly 2B)
        const int c = tid >> 3;                 // chunk 0..31
        const int i = tid & 7;                  // row of chunk matrix
        const int len = lengths[db];
        const int C = (T - 1 + NCH - 1) / NCH;

        float E[64];
        #pragma unroll
        for (int k = 0; k < 64; ++k) E[k] = __expf(__ldg(trans + k));

        float r[8];
        #pragma unroll
        for (int j = 0; j < 8; ++j) r[j] = (j == i) ? 1.0f : 0.0f;
        float off = 0.0f;

        const int t0 = 1 + c * C;
        const int t1 = min(t0 + C, len);
        const float* emb = em + (size_t)db * T * 8;

        for (int t = t0; t < t1; ++t) {
            float4 lo = __ldg((const float4*)(emb + t * 8));
            float4 hi = __ldg((const float4*)(emb + t * 8 + 4));
            float Em[8];
            Em[0] = __expf(lo.x); Em[1] = __expf(lo.y);
            Em[2] = __expf(lo.z); Em[3] = __expf(lo.w);
            Em[4] = __expf(hi.x); Em[5] = __expf(hi.y);
            Em[6] = __expf(hi.z); Em[7] = __expf(hi.w);

            float s[8];
            #pragma unroll
            for (int j = 0; j < 8; ++j) {
                float acc = r[0] * E[0 * 8 + j];
                #pragma unroll
                for (int kk = 1; kk < 8; ++kk) acc = fmaf(r[kk], E[kk * 8 + j], acc);
                s[j] = acc * Em[j];
            }
            #pragma unroll
            for (int j = 0; j < 8; ++j) r[j] = s[j];

            if (((t - t0) & 3) == 3) {
                float m = r[0];
                #pragma unroll
                for (int j = 1; j < 8; ++j) m = fmaxf(m, r[j]);
                float inv = __fdividef(1.0f, m);
                off += __logf(m);
                #pragma unroll
                for (int j = 0; j < 8; ++j) r[j] *= inv;
            }
        }

        #pragma unroll
        for (int j = 0; j < 8; ++j) {
            float lv = (r[j] > 0.0f) ? (__logf(r[j]) + off) : NEGF;
            g_LP[(((db * NCH) + c) * 8 + j) * 8 + i] = lv;
        }
    }

    // ---------------- Fused finish: last block folds chunks + reduces ----------------
    __threadfence();
    __syncthreads();
    if (tid == 0) {
        unsigned old = atomicAdd(&g_done, 1u);
        s_flag = (old == (unsigned)(2 * B - 1));
    }
    __syncthreads();
    if (s_flag) {
        __threadfence();
        const int  bq = min(tid >> 3, B - 1);   // clamp so all 256 threads run shfls
        const int  j  = tid & 7;
        const bool active = (tid >> 3) < B;

        float alpha = __ldg(bos + j) + __ldg(em + (size_t)bq * T * 8 + j);  // natural log
        const float* base = g_LP + (size_t)bq * NCH * 64 + j * 8;
        float4 plo[4], phi[4];
        #pragma unroll
        for (int kk = 0; kk < 4; ++kk) {
            plo[kk] = __ldg((const float4*)(base + kk * 64));
            phi[kk] = __ldg((const float4*)(base + kk * 64 + 4));
        }
        #pragma unroll 4
        for (int c = 0; c < NCH; ++c) {
            float4 lo = plo[c & 3], hi = phi[c & 3];
            int cn = c + 4;
            if (cn < NCH) {
                plo[c & 3] = __ldg((const float4*)(base + cn * 64));
                phi[c & 3] = __ldg((const float4*)(base + cn * 64 + 4));
            }
            float M[8] = {lo.x, lo.y, lo.z, lo.w, hi.x, hi.y, hi.z, hi.w};
            float v[8], m = -3.0e38f;
            #pragma unroll
            for (int i2 = 0; i2 < 8; ++i2) {
                float ai = __shfl_sync(0xffffffffu, alpha, i2, 8);
                v[i2] = ai + M[i2];
                m = fmaxf(m, v[i2]);
            }
            float s = 0.0f;
            #pragma unroll
            for (int i2 = 0; i2 < 8; ++i2) s += ex2f_((v[i2] - m) * LOG2E_F);
            alpha = m + lg2f_(s) * LN2_F;
        }
        float f = alpha + __ldg(eos + j);
        float m = f;
        #pragma unroll
        for (int d = 4; d >= 1; d >>= 1) m = fmaxf(m, __shfl_xor_sync(0xffffffffu, m, d, 8));
        float s = ex2f_((f - m) * LOG2E_F);
        #pragma unroll
        for (int d = 4; d >= 1; d >>= 1) s += __shfl_xor_sync(0xffffffffu, s, d, 8);
        float den = m + lg2f_(s) * LN2_F;

        if (active && j == 0) s_scratch[tid >> 3] = den - g_num[bq];
        __syncthreads();
        if (tid == 0) {
            float acc = 0.0f;
            for (int bb = 0; bb < B; ++bb) acc += s_scratch[bb];
            out[0] = acc / (float)B;
            g_done = 0;                         // reset for next graph replay
        }
    }
}

extern "C" void kernel_launch(void* const* d_in, const int* in_sizes, int n_in,
                              void* d_out, int out_size)
{
    const float* em     = (const float*)d_in[0];  // (B,T,8)
    const float* trans  = (const float*)d_in[1];  // (8,8)
    const float* bos    = (const float*)d_in[2];  // (8)
    const float* eos    = (const float*)d_in[3];  // (8)
    const int*   lens   = (const int*)  d_in[4];  // (B)
    const int*   tgts   = (const int*)  d_in[5];  // (B,L)
    const int*   tlens  = (const int*)  d_in[6];  // (B)
    float* out = (float*)d_out;

    const int B = in_sizes[4];                 // 16
    const int T = in_sizes[0] / (B * 8);       // 2048
    const int L = in_sizes[5] / B;             // 256

    const size_t smem = (size_t)3 * (T - 1) * sizeof(float4);  // boundary rings
    cudaFuncSetAttribute(ctccrf_fused, cudaFuncAttributeMaxDynamicSharedMemorySize, (int)smem);

    // Blocks [0,B): numerator (L/2 workers, linear-space, sentinel-ring skewed warps).
    // Blocks [B,2B): denominator phase A. Last-done block runs the finish fold.
    ctccrf_fused<<<2 * B, 256, smem>>>(em, trans, bos, eos, lens, tgts, tlens, out, B, T, L);
}

// round 7
// speedup vs baseline: 1.4484x; 1.2775x over previous
#include <cuda_runtime.h>
#include <math.h>

#define NEGF    (-1e30f)
#define MAXB    16
#define NCH     32
#define LOG2E_F 1.4426950408889634f
#define LN2_F   0.6931471805599453f
#define PEI_NONE (-1000000000)

// Scratch (static device arrays; no allocations allowed)
__device__ float    g_num[MAXB];                 // numerator logZ per batch (natural log)
__device__ float    g_LP[MAXB * NCH * 8 * 8];    // [b][c][j][i] log chunk matrices
__device__ unsigned g_done = 0;

// ---------------- helpers ----------------
__device__ __forceinline__ float ex2f_(float x) {
    float r; asm("ex2.approx.ftz.f32 %0, %1;" : "=f"(r) : "f"(x)); return r;
}
__device__ __forceinline__ float lg2f_(float x) {
    float r; asm("lg2.approx.ftz.f32 %0, %1;" : "=f"(r) : "f"(x)); return r;
}
// logaddexp in log2 domain: log2(2^a + 2^b)
__device__ __forceinline__ float lae2(float a, float b) {
    float m = fmaxf(a, b);
    float d = fminf(a, b) - m;            // <= 0
    return m + lg2f_(1.0f + ex2f_(d));
}
// volatile 128-bit shared ld/st (single LDS.128/STS.128; .x doubles as ready flag)
__device__ __forceinline__ float4 lds128v(const float4* p) {
    float4 v; unsigned a = (unsigned)__cvta_generic_to_shared(p);
    asm volatile("ld.volatile.shared.v4.f32 {%0,%1,%2,%3},[%4];"
                 : "=f"(v.x), "=f"(v.y), "=f"(v.z), "=f"(v.w) : "r"(a));
    return v;
}
__device__ __forceinline__ void sts128v(float4* p, float4 v) {
    unsigned a = (unsigned)__cvta_generic_to_shared(p);
    asm volatile("st.volatile.shared.v4.f32 [%0],{%1,%2,%3,%4};"
                 :: "r"(a), "f"(v.x), "f"(v.y), "f"(v.z), "f"(v.w));
}
__device__ __forceinline__ int isnanf_(float x) { return x != x; }

// One numerator step, LINEAR space with per-lane block exponent e (value = v * 2^e).
// Emissions come pre-exponentiated from the smem table `tab` (pair-interleaved
// layout: frame f, float index f*8 + 2*tg   -> (exp em[enter], exp em[extend])
// fetched as one LDS.64). No LDG, no MUFU in the hot loop.
#define NUM_STEP(T_, J_, CUR_, RESC_) do {                                     \
    float pe_ = __shfl_up_sync(0xffffffffu, ve1, 1);                           \
    float px_ = __shfl_up_sync(0xffffffffu, vx1, 1);                           \
    int  pei_ = __shfl_up_sync(0xffffffffu, e, 1);                             \
    if (lane == 0) { pe_ = (CUR_).x; px_ = (CUR_).y;                           \
                     pei_ = __float_as_int((CUR_).z); }                        \
    int d_  = pei_ - e;                                                        \
    int dp_ = max(d_, 0);                                                      \
    int dn_ = min(d_, 0);                                                      \
    float fo_ = __int_as_float((max(-dp_, -127) + 127) << 23);  /* own scale */\
    float fi_ = __int_as_float((max(dn_, -127) + 127) << 23);   /* in  scale */\
    e += dp_;                                                                  \
    float g0_ = fem0[J_].x * fi_;                                              \
    float g1_ = fem0[J_].y * fo_;                                              \
    float g2_ = fem1[J_].x * fo_;                                              \
    float g3_ = fem1[J_].y * fo_;                                              \
    float nve0_ = g0_ * fmaf(pe_, t_ee0, px_ * t_xe0);                         \
    float nvx0_ = g1_ * fmaf(ve0, t_ex0, vx0 * t_xx0);                         \
    float nve1_ = g2_ * fmaf(ve0, t_ee1, vx0 * t_xe1);                         \
    float nvx1_ = g3_ * fmaf(ve1, t_ex1, vx1 * t_xx1);                         \
    int fp_ = min((T_) + 4, len - 1);                                          \
    fem0[J_] = *(const float2*)(tab + fp_ * 8 + so0);                          \
    fem1[J_] = *(const float2*)(tab + fp_ * 8 + so1);                          \
    ve0 = nve0_; vx0 = nvx0_; ve1 = nve1_; vx1 = nvx1_;                        \
    if (lane == 31 && warp < 3 && (T_) <= lenm2)                               \
        sts128v(&rprod[(T_)], make_float4(ve1, vx1, __int_as_float(e), 0.f));  \
    if (RESC_) {                                                               \
        float m_ = fmaxf(fmaxf(ve0, vx0), fmaxf(ve1, vx1));                    \
        int mb_ = __float_as_int(m_);                                          \
        int ei_ = (mb_ == 0) ? 0 : ((mb_ >> 23) - 127);                        \
        float fr_ = __int_as_float((127 - ei_) << 23);                         \
        ve0 *= fr_; vx0 *= fr_; ve1 *= fr_; vx1 *= fr_;                        \
        e += ei_;                                                              \
    }                                                                          \
} while (0)

extern "C" __global__ void __launch_bounds__(256, 1)
ctccrf_fused(const float* __restrict__ em,      // (B,T,8)
             const float* __restrict__ trans,   // (8,8)
             const float* __restrict__ bos,     // (8)
             const float* __restrict__ eos,     // (8)
             const int*   __restrict__ lengths, // (B)
             const int*   __restrict__ targets, // (B,L)
             const int*   __restrict__ tlens,   // (B)
             float* __restrict__ out,
             int B, int T, int L)
{
    extern __shared__ char dsm[];
    __shared__ float    s_scratch[MAXB];
    __shared__ int      s_flag;
    __shared__ unsigned s_emflag;
    const int tid = threadIdx.x;
    const int RNn = T - 1;
    float4* dring = (float4*)dsm;                          // [3][T-1] boundary slots
    float*  tab   = (float*)(dsm + (size_t)3 * RNn * 16);  // [T][8] exp-emission table

    if ((int)blockIdx.x < B) {
        const int b = blockIdx.x;
        // ring init + flag init
        const float NANSENT = __int_as_float(0x7fc00000);
        for (int i = tid; i < 3 * RNn; i += 256)
            dring[i] = make_float4(NANSENT, 0.f, 0.f, 0.f);
        if (tid == 0) s_emflag = 0u;
        __syncthreads();

        if (tid >= 128) {
            // ---------- Emission preprocessor: warps 4-7 fill the exp table ----------
            const int p = tid - 128;
            const int FP = (T + 127) >> 7;     // frames per thread (16 for T=2048)
            const float* emb = em + (size_t)b * T * 8;
            const int f0 = p * FP;
            const int f1 = min(f0 + FP, T);
            for (int f = f0; f < f1; ++f) {
                float4 lo = __ldg((const float4*)(emb + f * 8));
                float4 hi = __ldg((const float4*)(emb + f * 8 + 4));
                float v0 = ex2f_(lo.x * LOG2E_F), v1 = ex2f_(lo.y * LOG2E_F);
                float v2 = ex2f_(lo.z * LOG2E_F), v3 = ex2f_(lo.w * LOG2E_F);
                float v4 = ex2f_(hi.x * LOG2E_F), v5 = ex2f_(hi.y * LOG2E_F);
                float v6 = ex2f_(hi.z * LOG2E_F), v7 = ex2f_(hi.w * LOG2E_F);
                // pair-interleaved: [s0,s4, s1,s5, s2,s6, s3,s7]
                *(float4*)(tab + f * 8)     = make_float4(v0, v4, v1, v5);
                *(float4*)(tab + f * 8 + 4) = make_float4(v2, v6, v3, v7);
            }
            asm volatile("bar.sync 1, 128;" ::: "memory");   // drains STS of all 4 warps
            if (tid == 128) *(volatile unsigned*)&s_emflag = 1u;
        } else if (tid < (L >> 1)) {
            // ------- Numerator workers: 128 threads, 2 lanes/thread, skewed warps -------
            const int k    = tid;
            const int lane = k & 31;
            const int warp = k >> 5;
            const int u0 = 2 * k, u1 = 2 * k + 1;

            const int len = lengths[b];
            const int lenm2 = len - 2;
            const int tg0 = __ldg(targets + b * L + u0);
            const int tg1 = __ldg(targets + b * L + u1);
            const int es0 = tg0, xs0 = tg0 + 4;
            const int es1 = tg1, xs1 = tg1 + 4;
            const int so0 = 2 * tg0;           // table pair offset (floats)
            const int so1 = 2 * tg1;
            const int tgp0 = (u0 == 0) ? tg0 : __ldg(targets + b * L + u0 - 1);

            // transitions in LINEAR space
            const float t_ee0 = __expf(__ldg(trans + tgp0 * 8 + es0));
            const float t_xe0 = __expf(__ldg(trans + (tgp0 + 4) * 8 + es0));
            const float t_ex0 = __expf(__ldg(trans + es0 * 8 + xs0));
            const float t_xx0 = __expf(__ldg(trans + xs0 * 8 + xs0));
            const float t_ee1 = __expf(__ldg(trans + tg0 * 8 + es1));  // prev of u1 is u0
            const float t_xe1 = __expf(__ldg(trans + (tg0 + 4) * 8 + es1));
            const float t_ex1 = __expf(__ldg(trans + es1 * 8 + xs1));
            const float t_xx1 = __expf(__ldg(trans + xs1 * 8 + xs1));

            const float* emb = em + (size_t)b * T * 8;
            float ve0 = (u0 == 0) ? __expf(__ldg(bos + es0) + __ldg(emb + es0)) : 0.f;
            float vx0 = 0.f, ve1 = 0.f, vx1 = 0.f;
            int e = 0;

            float4*       rprod = dring + (size_t)((warp < 3) ? warp : 0) * RNn;
            const float4* rcons = dring + (size_t)((warp > 0) ? (warp - 1) : 0) * RNn;

            // wait for the emission table (preprocessors finish in ~2-3 us)
            while (*(volatile unsigned*)&s_emflag == 0u) __nanosleep(64);

            // publish initial boundary (time 0)
            if (lane == 31 && warp < 3)
                sts128v(&rprod[0], make_float4(ve1, vx1, __int_as_float(e), 0.f));

            // emission prefetch for steps 1..4 (clamped), from table
            float2 fem0[4], fem1[4];
            #pragma unroll
            for (int j = 0; j < 4; ++j) {
                int tc = min(1 + j, len - 1);
                fem0[j] = *(const float2*)(tab + tc * 8 + so0);
                fem1[j] = *(const float2*)(tab + tc * 8 + so1);
            }

            const float4 W0C = make_float4(0.f, 0.f, __int_as_float(PEI_NONE), 0.f);
            float4 cur0 = W0C, cur1 = W0C, cur2 = W0C, cur3 = W0C;
            float4 nxt0 = W0C, nxt1 = W0C, nxt2 = W0C, nxt3 = W0C;
            if (lane == 0 && warp > 0) {
                cur0 = lds128v(&rcons[0]);
                cur1 = lds128v(&rcons[min(1, lenm2)]);
                cur2 = lds128v(&rcons[min(2, lenm2)]);
                cur3 = lds128v(&rcons[min(3, lenm2)]);
            }

            int t = 1;
            for (; t + 3 < len; t += 4) {
                if (lane == 0 && warp > 0) {
                    while (isnanf_(cur0.x) | isnanf_(cur1.x) | isnanf_(cur2.x) | isnanf_(cur3.x)) {
                        cur0 = lds128v(&rcons[t - 1]);
                        cur1 = lds128v(&rcons[t]);
                        cur2 = lds128v(&rcons[t + 1]);
                        cur3 = lds128v(&rcons[t + 2]);
                    }
                    nxt0 = lds128v(&rcons[min(t + 3, lenm2)]);
                    nxt1 = lds128v(&rcons[min(t + 4, lenm2)]);
                    nxt2 = lds128v(&rcons[min(t + 5, lenm2)]);
                    nxt3 = lds128v(&rcons[min(t + 6, lenm2)]);
                }
                NUM_STEP(t,     0, cur0, 0);
                NUM_STEP(t + 1, 1, cur1, 1);
                NUM_STEP(t + 2, 2, cur2, 0);
                NUM_STEP(t + 3, 3, cur3, 1);
                cur0 = nxt0; cur1 = nxt1; cur2 = nxt2; cur3 = nxt3;
            }
            // tail (<=3 steps; len uniform across block)
            if (t < len) {
                float4 bb = W0C;
                if (lane == 0 && warp > 0) { do { bb = lds128v(&rcons[t - 1]); } while (isnanf_(bb.x)); }
                NUM_STEP(t, 0, bb, 1); t++;
            }
            if (t < len) {
                float4 bb = W0C;
                if (lane == 0 && warp > 0) { do { bb = lds128v(&rcons[t - 1]); } while (isnanf_(bb.x)); }
                NUM_STEP(t, 1, bb, 1); t++;
            }
            if (t < len) {
                float4 bb = W0C;
                if (lane == 0 && warp > 0) { do { bb = lds128v(&rcons[t - 1]); } while (isnanf_(bb.x)); }
                NUM_STEP(t, 2, bb, 1); t++;
            }

            const int tl = __ldg(tlens + b);
            if (u0 == tl - 1) {
                float fe2 = lg2f_(ve0) + (float)e + __ldg(eos + es0) * LOG2E_F;
                float fx2 = lg2f_(vx0) + (float)e + __ldg(eos + xs0) * LOG2E_F;
                g_num[b] = lae2(fe2, fx2) * LN2_F;
            }
            if (u1 == tl - 1) {
                float fe2 = lg2f_(ve1) + (float)e + __ldg(eos + es1) * LOG2E_F;
                float fx2 = lg2f_(vx1) + (float)e + __ldg(eos + xs1) * LOG2E_F;
                g_num[b] = lae2(fe2, fx2) * LN2_F;
            }
        }
    } else {
        // ------------- Denominator Phase A: chunked 8x8 linear-space scan -------------
        const int db = blockIdx.x - B;          // batch (grid is exactly 2B)
        const int c = tid >> 3;                 // chunk 0..31
        const int i = tid & 7;                  // row of chunk matrix
        const int len = lengths[db];
        const int C = (T - 1 + NCH - 1) / NCH;

        float E[64];
        #pragma unroll
        for (int k = 0; k < 64; ++k) E[k] = __expf(__ldg(trans + k));

        float r[8];
        #pragma unroll
        for (int j = 0; j < 8; ++j) r[j] = (j == i) ? 1.0f : 0.0f;
        float off = 0.0f;

        const int t0 = 1 + c * C;
        const int t1 = min(t0 + C, len);
        const float* emb = em + (size_t)db * T * 8;

        for (int t = t0; t < t1; ++t) {
            float4 lo = __ldg((const float4*)(emb + t * 8));
            float4 hi = __ldg((const float4*)(emb + t * 8 + 4));
            float Em[8];
            Em[0] = __expf(lo.x); Em[1] = __expf(lo.y);
            Em[2] = __expf(lo.z); Em[3] = __expf(lo.w);
            Em[4] = __expf(hi.x); Em[5] = __expf(hi.y);
            Em[6] = __expf(hi.z); Em[7] = __expf(hi.w);

            float s[8];
            #pragma unroll
            for (int j = 0; j < 8; ++j) {
                float acc = r[0] * E[0 * 8 + j];
                #pragma unroll
                for (int kk = 1; kk < 8; ++kk) acc = fmaf(r[kk], E[kk * 8 + j], acc);
                s[j] = acc * Em[j];
            }
            #pragma unroll
            for (int j = 0; j < 8; ++j) r[j] = s[j];

            if (((t - t0) & 3) == 3) {
                float m = r[0];
                #pragma unroll
                for (int j = 1; j < 8; ++j) m = fmaxf(m, r[j]);
                float inv = __fdividef(1.0f, m);
                off += __logf(m);
                #pragma unroll
                for (int j = 0; j < 8; ++j) r[j] *= inv;
            }
        }

        #pragma unroll
        for (int j = 0; j < 8; ++j) {
            float lv = (r[j] > 0.0f) ? (__logf(r[j]) + off) : NEGF;
            g_LP[(((db * NCH) + c) * 8 + j) * 8 + i] = lv;
        }
    }

    // ---------------- Fused finish: last block folds chunks + reduces ----------------
    __threadfence();
    __syncthreads();
    if (tid == 0) {
        unsigned old = atomicAdd(&g_done, 1u);
        s_flag = (old == (unsigned)(2 * B - 1));
    }
    __syncthreads();
    if (s_flag) {
        __threadfence();
        const int  bq = min(tid >> 3, B - 1);   // clamp so all 256 threads run shfls
        const int  j  = tid & 7;
        const bool active = (tid >> 3) < B;

        float alpha = __ldg(bos + j) + __ldg(em + (size_t)bq * T * 8 + j);  // natural log
        const float* base = g_LP + (size_t)bq * NCH * 64 + j * 8;
        float4 plo[4], phi[4];
        #pragma unroll
        for (int kk = 0; kk < 4; ++kk) {
            plo[kk] = __ldg((const float4*)(base + kk * 64));
            phi[kk] = __ldg((const float4*)(base + kk * 64 + 4));
        }
        #pragma unroll 4
        for (int c = 0; c < NCH; ++c) {
            float4 lo = plo[c & 3], hi = phi[c & 3];
            int cn = c + 4;
            if (cn < NCH) {
                plo[c & 3] = __ldg((const float4*)(base + cn * 64));
                phi[c & 3] = __ldg((const float4*)(base + cn * 64 + 4));
            }
            float M[8] = {lo.x, lo.y, lo.z, lo.w, hi.x, hi.y, hi.z, hi.w};
            float v[8], m = -3.0e38f;
            #pragma unroll
            for (int i2 = 0; i2 < 8; ++i2) {
                float ai = __shfl_sync(0xffffffffu, alpha, i2, 8);
                v[i2] = ai + M[i2];
                m = fmaxf(m, v[i2]);
            }
            float s = 0.0f;
            #pragma unroll
            for (int i2 = 0; i2 < 8; ++i2) s += ex2f_((v[i2] - m) * LOG2E_F);
            alpha = m + lg2f_(s) * LN2_F;
        }
        float f = alpha + __ldg(eos + j);
        float m = f;
        #pragma unroll
        for (int d = 4; d >= 1; d >>= 1) m = fmaxf(m, __shfl_xor_sync(0xffffffffu, m, d, 8));
        float s = ex2f_((f - m) * LOG2E_F);
        #pragma unroll
        for (int d = 4; d >= 1; d >>= 1) s += __shfl_xor_sync(0xffffffffu, s, d, 8);
        float den = m + lg2f_(s) * LN2_F;

        if (active && j == 0) s_scratch[tid >> 3] = den - g_num[bq];
        __syncthreads();
        if (tid == 0) {
            float acc = 0.0f;
            for (int bb = 0; bb < B; ++bb) acc += s_scratch[bb];
            out[0] = acc / (float)B;
            g_done = 0;                         // reset for next graph replay
        }
    }
}

extern "C" void kernel_launch(void* const* d_in, const int* in_sizes, int n_in,
                              void* d_out, int out_size)
{
    const float* em     = (const float*)d_in[0];  // (B,T,8)
    const float* trans  = (const float*)d_in[1];  // (8,8)
    const float* bos    = (const float*)d_in[2];  // (8)
    const float* eos    = (const float*)d_in[3];  // (8)
    const int*   lens   = (const int*)  d_in[4];  // (B)
    const int*   tgts   = (const int*)  d_in[5];  // (B,L)
    const int*   tlens  = (const int*)  d_in[6];  // (B)
    float* out = (float*)d_out;

    const int B = in_sizes[4];                 // 16
    const int T = in_sizes[0] / (B * 8);       // 2048
    const int L = in_sizes[5] / B;             // 256

    // dynamic smem: boundary rings [3][T-1] float4  +  exp-emission table [T][8] float
    const size_t smem = (size_t)3 * (T - 1) * sizeof(float4) + (size_t)T * 8 * sizeof(float);
    cudaFuncSetAttribute(ctccrf_fused, cudaFuncAttributeMaxDynamicSharedMemorySize, (int)smem);

    // Blocks [0,B): numerator (128 workers + 4 emission-preproc warps).
    // Blocks [B,2B): denominator phase A. Last-done block runs the finish fold.
    ctccrf_fused<<<2 * B, 256, smem>>>(em, trans, bos, eos, lens, tgts, tlens, out, B, T, L);
}

// round 8
// speedup vs baseline: 1.4875x; 1.0270x over previous
#include <cuda_runtime.h>
#include <math.h>

#define NEGF    (-1e30f)
#define MAXB    16
#define NCH     32
#define LOG2E_F 1.4426950408889634f
#define LN2_F   0.6931471805599453f
#define PEI_NONE (-1000000000)

// Scratch (static device arrays; no allocations allowed)
__device__ float    g_num[MAXB];                 // numerator logZ per batch (natural log)
__device__ float    g_LP[MAXB * NCH * 8 * 8];    // [b][c][j][i] log chunk matrices
__device__ unsigned g_done = 0;

// ---------------- helpers ----------------
__device__ __forceinline__ float ex2f_(float x) {
    float r; asm("ex2.approx.ftz.f32 %0, %1;" : "=f"(r) : "f"(x)); return r;
}
__device__ __forceinline__ float lg2f_(float x) {
    float r; asm("lg2.approx.ftz.f32 %0, %1;" : "=f"(r) : "f"(x)); return r;
}
// logaddexp in log2 domain: log2(2^a + 2^b)
__device__ __forceinline__ float lae2(float a, float b) {
    float m = fmaxf(a, b);
    float d = fminf(a, b) - m;            // <= 0
    return m + lg2f_(1.0f + ex2f_(d));
}
// volatile 128-bit shared ld/st (single LDS.128/STS.128; .x doubles as ready flag)
__device__ __forceinline__ float4 lds128v(const float4* p) {
    float4 v; unsigned a = (unsigned)__cvta_generic_to_shared(p);
    asm volatile("ld.volatile.shared.v4.f32 {%0,%1,%2,%3},[%4];"
                 : "=f"(v.x), "=f"(v.y), "=f"(v.z), "=f"(v.w) : "r"(a));
    return v;
}
__device__ __forceinline__ void sts128v(float4* p, float4 v) {
    unsigned a = (unsigned)__cvta_generic_to_shared(p);
    asm volatile("st.volatile.shared.v4.f32 [%0],{%1,%2,%3,%4};"
                 :: "r"(a), "f"(v.x), "f"(v.y), "f"(v.z), "f"(v.w));
}
// predicated volatile STS.128: all lanes issue it, only doit!=0 lanes store.
// Keeps the asm-volatile store OUT of a divergent C++ branch (no BSSY/BSYNC).
__device__ __forceinline__ void sts128v_pred(float4* p, float4 v, int doit) {
    unsigned a = (unsigned)__cvta_generic_to_shared(p);
    asm volatile("{ .reg .pred p0;\n\t"
                 "setp.ne.u32 p0, %0, 0;\n\t"
                 "@p0 st.volatile.shared.v4.f32 [%1],{%2,%3,%4,%5}; }"
                 :: "r"(doit), "r"(a), "f"(v.x), "f"(v.y), "f"(v.z), "f"(v.w));
}
__device__ __forceinline__ int isnanf_(float x) { return x != x; }

// One numerator step, LINEAR space with per-lane block exponent e (value = v * 2^e).
// Emissions come pre-exponentiated from the smem table `tab`. No LDG, no MUFU,
// and no divergent branch (publish is a predicated STS).
#define NUM_STEP(T_, J_, CUR_, RESC_) do {                                     \
    float pe_ = __shfl_up_sync(0xffffffffu, ve1, 1);                           \
    float px_ = __shfl_up_sync(0xffffffffu, vx1, 1);                           \
    int  pei_ = __shfl_up_sync(0xffffffffu, e, 1);                             \
    if (lane == 0) { pe_ = (CUR_).x; px_ = (CUR_).y;                           \
                     pei_ = __float_as_int((CUR_).z); }                        \
    int d_  = pei_ - e;                                                        \
    int dp_ = max(d_, 0);                                                      \
    int dn_ = min(d_, 0);                                                      \
    float fo_ = __int_as_float((max(-dp_, -127) + 127) << 23);  /* own scale */\
    float fi_ = __int_as_float((max(dn_, -127) + 127) << 23);   /* in  scale */\
    e += dp_;                                                                  \
    float g0_ = fem0[J_].x * fi_;                                              \
    float g1_ = fem0[J_].y * fo_;                                              \
    float g2_ = fem1[J_].x * fo_;                                              \
    float g3_ = fem1[J_].y * fo_;                                              \
    float nve0_ = g0_ * fmaf(pe_, t_ee0, px_ * t_xe0);                         \
    float nvx0_ = g1_ * fmaf(ve0, t_ex0, vx0 * t_xx0);                         \
    float nve1_ = g2_ * fmaf(ve0, t_ee1, vx0 * t_xe1);                         \
    float nvx1_ = g3_ * fmaf(ve1, t_ex1, vx1 * t_xx1);                         \
    int fp_ = min((T_) + 4, len - 1);                                          \
    fem0[J_] = *(const float2*)(tab + fp_ * 8 + so0);                          \
    fem1[J_] = *(const float2*)(tab + fp_ * 8 + so1);                          \
    ve0 = nve0_; vx0 = nvx0_; ve1 = nve1_; vx1 = nvx1_;                        \
    sts128v_pred(&rprod[(T_)],                                                 \
                 make_float4(ve1, vx1, __int_as_float(e), 0.f),                \
                 pubmask & (int)((T_) <= lenm2));                              \
    if (RESC_) {                                                               \
        float m_ = fmaxf(fmaxf(ve0, vx0), fmaxf(ve1, vx1));                    \
        int mb_ = __float_as_int(m_);                                          \
        int ei_ = (mb_ == 0) ? 0 : ((mb_ >> 23) - 127);                        \
        float fr_ = __int_as_float((127 - ei_) << 23);                         \
        ve0 *= fr_; vx0 *= fr_; ve1 *= fr_; vx1 *= fr_;                        \
        e += ei_;                                                              \
    }                                                                          \
} while (0)

extern "C" __global__ void __launch_bounds__(256, 1)
ctccrf_fused(const float* __restrict__ em,      // (B,T,8)
             const float* __restrict__ trans,   // (8,8)
             const float* __restrict__ bos,     // (8)
             const float* __restrict__ eos,     // (8)
             const int*   __restrict__ lengths, // (B)
             const int*   __restrict__ targets, // (B,L)
             const int*   __restrict__ tlens,   // (B)
             float* __restrict__ out,
             int B, int T, int L)
{
    extern __shared__ char dsm[];
    __shared__ float    s_scratch[MAXB];
    __shared__ int      s_flag;
    __shared__ unsigned s_emflag;
    const int tid = threadIdx.x;
    const int RNn = T - 1;
    float4* dring = (float4*)dsm;                          // [3][T-1] boundary slots
    float*  tab   = (float*)(dsm + (size_t)3 * RNn * 16);  // [T][8] exp-emission table

    if ((int)blockIdx.x < B) {
        const int b = blockIdx.x;
        // ring init + flag init
        const float NANSENT = __int_as_float(0x7fc00000);
        for (int i = tid; i < 3 * RNn; i += 256)
            dring[i] = make_float4(NANSENT, 0.f, 0.f, 0.f);
        if (tid == 0) s_emflag = 0u;
        __syncthreads();

        if (tid >= 128) {
            // ---------- Emission preprocessor: warps 4-7 fill the exp table ----------
            const int p = tid - 128;
            const int FP = (T + 127) >> 7;     // frames per thread (16 for T=2048)
            const float* emb = em + (size_t)b * T * 8;
            const int f0 = p * FP;
            const int f1 = min(f0 + FP, T);
            for (int f = f0; f < f1; ++f) {
                float4 lo = __ldg((const float4*)(emb + f * 8));
                float4 hi = __ldg((const float4*)(emb + f * 8 + 4));
                float v0 = ex2f_(lo.x * LOG2E_F), v1 = ex2f_(lo.y * LOG2E_F);
                float v2 = ex2f_(lo.z * LOG2E_F), v3 = ex2f_(lo.w * LOG2E_F);
                float v4 = ex2f_(hi.x * LOG2E_F), v5 = ex2f_(hi.y * LOG2E_F);
                float v6 = ex2f_(hi.z * LOG2E_F), v7 = ex2f_(hi.w * LOG2E_F);
                // pair-interleaved: [s0,s4, s1,s5, s2,s6, s3,s7]
                *(float4*)(tab + f * 8)     = make_float4(v0, v4, v1, v5);
                *(float4*)(tab + f * 8 + 4) = make_float4(v2, v6, v3, v7);
            }
            asm volatile("bar.sync 1, 128;" ::: "memory");   // drains STS of all 4 warps
            if (tid == 128) *(volatile unsigned*)&s_emflag = 1u;
        } else if (tid < (L >> 1)) {
            // ------- Numerator workers: 128 threads, 2 lanes/thread, skewed warps -------
            const int k    = tid;
            const int lane = k & 31;
            const int warp = k >> 5;
            const int u0 = 2 * k, u1 = 2 * k + 1;

            const int len = lengths[b];
            const int lenm2 = len - 2;
            const int tg0 = __ldg(targets + b * L + u0);
            const int tg1 = __ldg(targets + b * L + u1);
            const int es0 = tg0, xs0 = tg0 + 4;
            const int es1 = tg1, xs1 = tg1 + 4;
            const int so0 = 2 * tg0;           // table pair offset (floats)
            const int so1 = 2 * tg1;
            const int tgp0 = (u0 == 0) ? tg0 : __ldg(targets + b * L + u0 - 1);
            const int pubmask = (int)(lane == 31) & (int)(warp < 3);

            // transitions in LINEAR space
            const float t_ee0 = __expf(__ldg(trans + tgp0 * 8 + es0));
            const float t_xe0 = __expf(__ldg(trans + (tgp0 + 4) * 8 + es0));
            const float t_ex0 = __expf(__ldg(trans + es0 * 8 + xs0));
            const float t_xx0 = __expf(__ldg(trans + xs0 * 8 + xs0));
            const float t_ee1 = __expf(__ldg(trans + tg0 * 8 + es1));  // prev of u1 is u0
            const float t_xe1 = __expf(__ldg(trans + (tg0 + 4) * 8 + es1));
            const float t_ex1 = __expf(__ldg(trans + es1 * 8 + xs1));
            const float t_xx1 = __expf(__ldg(trans + xs1 * 8 + xs1));

            const float* emb = em + (size_t)b * T * 8;
            float ve0 = (u0 == 0) ? __expf(__ldg(bos + es0) + __ldg(emb + es0)) : 0.f;
            float vx0 = 0.f, ve1 = 0.f, vx1 = 0.f;
            int e = 0;

            float4*       rprod = dring + (size_t)((warp < 3) ? warp : 0) * RNn;
            const float4* rcons = dring + (size_t)((warp > 0) ? (warp - 1) : 0) * RNn;

            // wait for the emission table (preprocessors finish in ~2-3 us)
            while (*(volatile unsigned*)&s_emflag == 0u) __nanosleep(64);

            // publish initial boundary (time 0)
            if (lane == 31 && warp < 3)
                sts128v(&rprod[0], make_float4(ve1, vx1, __int_as_float(e), 0.f));

            // emission prefetch for steps 1..4 (clamped), from table
            float2 fem0[4], fem1[4];
            #pragma unroll
            for (int j = 0; j < 4; ++j) {
                int tc = min(1 + j, len - 1);
                fem0[j] = *(const float2*)(tab + tc * 8 + so0);
                fem1[j] = *(const float2*)(tab + tc * 8 + so1);
            }

            const float4 W0C = make_float4(0.f, 0.f, __int_as_float(PEI_NONE), 0.f);
            float4 cur0 = W0C, cur1 = W0C, cur2 = W0C, cur3 = W0C;
            float4 nxt0 = W0C, nxt1 = W0C, nxt2 = W0C, nxt3 = W0C;
            // ALL lanes poll the same slots (smem broadcast) -> warp-uniform branches
            if (warp > 0) {
                cur0 = lds128v(&rcons[0]);
                cur1 = lds128v(&rcons[min(1, lenm2)]);
                cur2 = lds128v(&rcons[min(2, lenm2)]);
                cur3 = lds128v(&rcons[min(3, lenm2)]);
            }

            int t = 1;
            for (; t + 3 < len; t += 4) {
                if (warp > 0) {
                    while (isnanf_(cur0.x) | isnanf_(cur1.x) | isnanf_(cur2.x) | isnanf_(cur3.x)) {
                        cur0 = lds128v(&rcons[t - 1]);
                        cur1 = lds128v(&rcons[t]);
                        cur2 = lds128v(&rcons[t + 1]);
                        cur3 = lds128v(&rcons[t + 2]);
                    }
                    nxt0 = lds128v(&rcons[min(t + 3, lenm2)]);
                    nxt1 = lds128v(&rcons[min(t + 4, lenm2)]);
                    nxt2 = lds128v(&rcons[min(t + 5, lenm2)]);
                    nxt3 = lds128v(&rcons[min(t + 6, lenm2)]);
                }
                NUM_STEP(t,     0, cur0, 0);
                NUM_STEP(t + 1, 1, cur1, 1);
                NUM_STEP(t + 2, 2, cur2, 0);
                NUM_STEP(t + 3, 3, cur3, 1);
                cur0 = nxt0; cur1 = nxt1; cur2 = nxt2; cur3 = nxt3;
            }
            // tail (<=3 steps; len uniform across block)
            if (t < len) {
                float4 bb = W0C;
                if (warp > 0) { do { bb = lds128v(&rcons[t - 1]); } while (isnanf_(bb.x)); }
                NUM_STEP(t, 0, bb, 1); t++;
            }
            if (t < len) {
                float4 bb = W0C;
                if (warp > 0) { do { bb = lds128v(&rcons[t - 1]); } while (isnanf_(bb.x)); }
                NUM_STEP(t, 1, bb, 1); t++;
            }
            if (t < len) {
                float4 bb = W0C;
                if (warp > 0) { do { bb = lds128v(&rcons[t - 1]); } while (isnanf_(bb.x)); }
                NUM_STEP(t, 2, bb, 1); t++;
            }

            const int tl = __ldg(tlens + b);
            if (u0 == tl - 1) {
                float fe2 = lg2f_(ve0) + (float)e + __ldg(eos + es0) * LOG2E_F;
                float fx2 = lg2f_(vx0) + (float)e + __ldg(eos + xs0) * LOG2E_F;
                g_num[b] = lae2(fe2, fx2) * LN2_F;
            }
            if (u1 == tl - 1) {
                float fe2 = lg2f_(ve1) + (float)e + __ldg(eos + es1) * LOG2E_F;
                float fx2 = lg2f_(vx1) + (float)e + __ldg(eos + xs1) * LOG2E_F;
                g_num[b] = lae2(fe2, fx2) * LN2_F;
            }
        }
    } else {
        // ------------- Denominator Phase A: chunked 8x8 linear-space scan -------------
        const int db = blockIdx.x - B;          // batch (grid is exactly 2B)
        const int c = tid >> 3;                 // chunk 0..31
        const int i = tid & 7;                  // row of chunk matrix
        const int len = lengths[db];
        const int C = (T - 1 + NCH - 1) / NCH;

        float E[64];
        #pragma unroll
        for (int k = 0; k < 64; ++k) E[k] = __expf(__ldg(trans + k));

        float r[8];
        #pragma unroll
        for (int j = 0; j < 8; ++j) r[j] = (j == i) ? 1.0f : 0.0f;
        float off = 0.0f;

        const int t0 = 1 + c * C;
        const int t1 = min(t0 + C, len);
        const float* emb = em + (size_t)db * T * 8;

        for (int t = t0; t < t1; ++t) {
            float4 lo = __ldg((const float4*)(emb + t * 8));
            float4 hi = __ldg((const float4*)(emb + t * 8 + 4));
            float Em[8];
            Em[0] = __expf(lo.x); Em[1] = __expf(lo.y);
            Em[2] = __expf(lo.z); Em[3] = __expf(lo.w);
            Em[4] = __expf(hi.x); Em[5] = __expf(hi.y);
            Em[6] = __expf(hi.z); Em[7] = __expf(hi.w);

            float s[8];
            #pragma unroll
            for (int j = 0; j < 8; ++j) {
                float acc = r[0] * E[0 * 8 + j];
                #pragma unroll
                for (int kk = 1; kk < 8; ++kk) acc = fmaf(r[kk], E[kk * 8 + j], acc);
                s[j] = acc * Em[j];
            }
            #pragma unroll
            for (int j = 0; j < 8; ++j) r[j] = s[j];

            if (((t - t0) & 3) == 3) {
                float m = r[0];
                #pragma unroll
                for (int j = 1; j < 8; ++j) m = fmaxf(m, r[j]);
                float inv = __fdividef(1.0f, m);
                off += __logf(m);
                #pragma unroll
                for (int j = 0; j < 8; ++j) r[j] *= inv;
            }
        }

        #pragma unroll
        for (int j = 0; j < 8; ++j) {
            float lv = (r[j] > 0.0f) ? (__logf(r[j]) + off) : NEGF;
            g_LP[(((db * NCH) + c) * 8 + j) * 8 + i] = lv;
        }
    }

    // ---------------- Fused finish: last block folds chunks + reduces ----------------
    __threadfence();
    __syncthreads();
    if (tid == 0) {
        unsigned old = atomicAdd(&g_done, 1u);
        s_flag = (old == (unsigned)(2 * B - 1));
    }
    __syncthreads();
    if (s_flag) {
        __threadfence();
        const int  bq = min(tid >> 3, B - 1);   // clamp so all 256 threads run shfls
        const int  j  = tid & 7;
        const bool active = (tid >> 3) < B;

        float alpha = __ldg(bos + j) + __ldg(em + (size_t)bq * T * 8 + j);  // natural log
        const float* base = g_LP + (size_t)bq * NCH * 64 + j * 8;
        float4 plo[4], phi[4];
        #pragma unroll
        for (int kk = 0; kk < 4; ++kk) {
            plo[kk] = __ldg((const float4*)(base + kk * 64));
            phi[kk] = __ldg((const float4*)(base + kk * 64 + 4));
        }
        #pragma unroll 4
        for (int c = 0; c < NCH; ++c) {
            float4 lo = plo[c & 3], hi = phi[c & 3];
            int cn = c + 4;
            if (cn < NCH) {
                plo[c & 3] = __ldg((const float4*)(base + cn * 64));
                phi[c & 3] = __ldg((const float4*)(base + cn * 64 + 4));
            }
            float M[8] = {lo.x, lo.y, lo.z, lo.w, hi.x, hi.y, hi.z, hi.w};
            float v[8], m = -3.0e38f;
            #pragma unroll
            for (int i2 = 0; i2 < 8; ++i2) {
                float ai = __shfl_sync(0xffffffffu, alpha, i2, 8);
                v[i2] = ai + M[i2];
                m = fmaxf(m, v[i2]);
            }
            float s = 0.0f;
            #pragma unroll
            for (int i2 = 0; i2 < 8; ++i2) s += ex2f_((v[i2] - m) * LOG2E_F);
            alpha = m + lg2f_(s) * LN2_F;
        }
        float f = alpha + __ldg(eos + j);
        float m = f;
        #pragma unroll
        for (int d = 4; d >= 1; d >>= 1) m = fmaxf(m, __shfl_xor_sync(0xffffffffu, m, d, 8));
        float s = ex2f_((f - m) * LOG2E_F);
        #pragma unroll
        for (int d = 4; d >= 1; d >>= 1) s += __shfl_xor_sync(0xffffffffu, s, d, 8);
        float den = m + lg2f_(s) * LN2_F;

        if (active && j == 0) s_scratch[tid >> 3] = den - g_num[bq];
        __syncthreads();
        if (tid == 0) {
            float acc = 0.0f;
            for (int bb = 0; bb < B; ++bb) acc += s_scratch[bb];
            out[0] = acc / (float)B;
            g_done = 0;                         // reset for next graph replay
        }
    }
}

extern "C" void kernel_launch(void* const* d_in, const int* in_sizes, int n_in,
                              void* d_out, int out_size)
{
    const float* em     = (const float*)d_in[0];  // (B,T,8)
    const float* trans  = (const float*)d_in[1];  // (8,8)
    const float* bos    = (const float*)d_in[2];  // (8)
    const float* eos    = (const float*)d_in[3];  // (8)
    const int*   lens   = (const int*)  d_in[4];  // (B)
    const int*   tgts   = (const int*)  d_in[5];  // (B,L)
    const int*   tlens  = (const int*)  d_in[6];  // (B)
    float* out = (float*)d_out;

    const int B = in_sizes[4];                 // 16
    const int T = in_sizes[0] / (B * 8);       // 2048
    const int L = in_sizes[5] / B;             // 256

    // dynamic smem: boundary rings [3][T-1] float4  +  exp-emission table [T][8] float
    const size_t smem = (size_t)3 * (T - 1) * sizeof(float4) + (size_t)T * 8 * sizeof(float);
    cudaFuncSetAttribute(ctccrf_fused, cudaFuncAttributeMaxDynamicSharedMemorySize, (int)smem);

    // Blocks [0,B): numerator (128 workers + 4 emission-preproc warps).
    // Blocks [B,2B): denominator phase A. Last-done block runs the finish fold.
    ctccrf_fused<<<2 * B, 256, smem>>>(em, trans, bos, eos, lens, tgts, tlens, out, B, T, L);
}